// round 1
// baseline (speedup 1.0000x reference)
#include <cuda_runtime.h>
#include <cstdint>
#include <cstddef>

// ============================================================================
// JAX PRNG variant: 1 = partitionable threefry (JAX >= 0.4.36 default),
//                   0 = legacy "original" split-halves scheme.
// ============================================================================
#define JAX_PARTITIONABLE 1

constexpr int S  = 10;
constexpr int D  = 512;
constexpr int NQ = 4096;
constexpr int NP = 1024;

// ------------------------- scratch (__device__ globals) ---------------------
__device__ float g_W[S * D * D];                  // sampled weights  [s][d][e]
__device__ float g_b[S * D];                      // sampled biases   [s][e]
__device__ float g_tq[(size_t)S * NQ * D];        // transformed q    [s][q][e]
__device__ float g_sqq[S * NQ];                   // ||tq||^2         [s][q]
__device__ float g_Pt[D * NP];                    // prototypes^T     [e][p]
__device__ float g_sqp[NP];                       // ||p||^2          [p]
__device__ float g_dists[(size_t)S * NQ * NP];    // dists            [s][q][p]

// ------------------------------ Threefry-2x32 -------------------------------
__host__ __device__ __forceinline__ unsigned rotl32(unsigned x, int d) {
    return (x << d) | (x >> (32 - d));
}

__host__ __device__ __forceinline__ void tf2x32(unsigned k0, unsigned k1,
                                                unsigned &x0, unsigned &x1) {
    unsigned k2 = k0 ^ k1 ^ 0x1BD11BDAu;
    x0 += k0; x1 += k1;
#define TFR(r) { x0 += x1; x1 = rotl32(x1, r) ^ x0; }
    TFR(13) TFR(15) TFR(26) TFR(6)   x0 += k1; x1 += k2 + 1u;
    TFR(17) TFR(29) TFR(16) TFR(24)  x0 += k2; x1 += k0 + 2u;
    TFR(13) TFR(15) TFR(26) TFR(6)   x0 += k0; x1 += k1 + 3u;
    TFR(17) TFR(29) TFR(16) TFR(24)  x0 += k1; x1 += k2 + 4u;
    TFR(13) TFR(15) TFR(26) TFR(6)   x0 += k2; x1 += k0 + 5u;
#undef TFR
}

// 32-bit random bits for flat element index i (matches jax random_bits)
__device__ __forceinline__ unsigned jax_bits32(unsigned k0, unsigned k1,
                                               unsigned i, unsigned total) {
#if JAX_PARTITIONABLE
    unsigned x0 = 0u, x1 = i;   // counter = uint64 i -> (hi, lo)
    tf2x32(k0, k1, x0, x1);
    return x0 ^ x1;
#else
    unsigned half = total >> 1;
    unsigned c0, c1; bool take0;
    if (i < half) { c0 = i;        c1 = i + half; take0 = true;  }
    else          { c0 = i - half; c1 = i;        take0 = false; }
    tf2x32(k0, k1, c0, c1);
    return take0 ? c0 : c1;
#endif
}

// --------------------------- XLA ErfInv32 (Giles) ---------------------------
__device__ __forceinline__ float erfinv_xla(float x) {
    float w = -log1pf(-x * x);
    float p;
    if (w < 5.0f) {
        w -= 2.5f;
        p = 2.81022636e-08f;
        p = fmaf(p, w, 3.43273939e-07f);
        p = fmaf(p, w, -3.5233877e-06f);
        p = fmaf(p, w, -4.39150654e-06f);
        p = fmaf(p, w, 0.00021858087f);
        p = fmaf(p, w, -0.00125372503f);
        p = fmaf(p, w, -0.00417768164f);
        p = fmaf(p, w, 0.246640727f);
        p = fmaf(p, w, 1.50140941f);
    } else {
        w = sqrtf(w) - 3.0f;
        p = -0.000200214257f;
        p = fmaf(p, w, 0.000100950558f);
        p = fmaf(p, w, 0.00134934322f);
        p = fmaf(p, w, -0.00367342844f);
        p = fmaf(p, w, 0.00573950773f);
        p = fmaf(p, w, -0.0076224613f);
        p = fmaf(p, w, 0.00943887047f);
        p = fmaf(p, w, 1.00167406f);
        p = fmaf(p, w, 2.83297682f);
    }
    return p * x;
}

// bits -> N(0,1) sample, exactly like jax.random.normal (float32)
__device__ __forceinline__ float bits_to_normal(unsigned bits) {
    float f = __uint_as_float((bits >> 9) | 0x3F800000u) - 1.0f;   // [0,1)
    float u = fmaxf(-0.99999994f, f * 2.0f - 0.99999994f);         // (-1,1)
    return 1.41421356237f * erfinv_xla(u);
}

// ------------------------------ sample kernels ------------------------------
__global__ void gen_w_kernel(const float* __restrict__ wmu,
                             const float* __restrict__ wrho,
                             unsigned k0, unsigned k1) {
    int i = blockIdx.x * blockDim.x + threadIdx.x;
    if (i >= S * D * D) return;
    unsigned bits = jax_bits32(k0, k1, (unsigned)i, (unsigned)(S * D * D));
    float eps = bits_to_normal(bits);
    int j = i & (D * D - 1);
    g_W[i] = fmaf(log1pf(expf(wrho[j])), eps, wmu[j]);
}

__global__ void gen_b_kernel(const float* __restrict__ bmu,
                             const float* __restrict__ brho,
                             unsigned k0, unsigned k1) {
    int i = blockIdx.x * blockDim.x + threadIdx.x;
    if (i >= S * D) return;
    unsigned bits = jax_bits32(k0, k1, (unsigned)i, (unsigned)(S * D));
    float eps = bits_to_normal(bits);
    int j = i & (D - 1);
    g_b[i] = fmaf(log1pf(expf(brho[j])), eps, bmu[j]);
}

// ------------------------------ prep kernels --------------------------------
__global__ void prep_pt_kernel(const float* __restrict__ P) {
    int idx = blockIdx.x * 256 + threadIdx.x;      // over D*NP
    int e = idx / NP, p = idx & (NP - 1);
    g_Pt[idx] = P[p * D + e];
}

__global__ void sqp_kernel(const float* __restrict__ P) {
    int p = blockIdx.x * 8 + (threadIdx.x >> 5);
    int lane = threadIdx.x & 31;
    const float* row = P + (size_t)p * D;
    float s = 0.f;
    for (int e = lane; e < D; e += 32) { float v = row[e]; s = fmaf(v, v, s); }
    #pragma unroll
    for (int o = 16; o; o >>= 1) s += __shfl_xor_sync(0xffffffffu, s, o);
    if (lane == 0) g_sqp[p] = s;
}

__global__ void sqq_kernel() {
    int row = blockIdx.x * 8 + (threadIdx.x >> 5);   // over S*NQ rows of g_tq
    int lane = threadIdx.x & 31;
    const float* r = g_tq + (size_t)row * D;
    float s = 0.f;
    for (int e = lane; e < D; e += 32) { float v = r[e]; s = fmaf(v, v, s); }
    #pragma unroll
    for (int o = 16; o; o >>= 1) s += __shfl_xor_sync(0xffffffffu, s, o);
    if (lane == 0) g_sqq[row] = s;
}

// ------------------------------ GEMM (fp32) ---------------------------------
// 128x128 block tile, BK=16, 256 threads, 8x8 per thread. All dims divide.
// EPI=0: C = X @ W_s + b_s          (M=NQ, N=D,  K=D)   -> g_tq
// EPI=1: dist = sqrt(q2+p2-2*(tq_s @ Pt))  (M=NQ, N=NP, K=D) -> g_dists
template <int EPI>
__global__ __launch_bounds__(256) void gemm128(const float* __restrict__ X) {
    constexpr int N = (EPI == 0) ? D : NP;
    constexpr int K = D;

    const int s = blockIdx.z;
    const float* __restrict__ A = (EPI == 0) ? X : (g_tq + (size_t)s * NQ * D);
    const float* __restrict__ B = (EPI == 0) ? (g_W + (size_t)s * D * D) : g_Pt;
    float* __restrict__ C = (EPI == 0) ? (g_tq + (size_t)s * NQ * D)
                                       : (g_dists + (size_t)s * NQ * NP);

    __shared__ float As[16][132];   // padded: transposed A tile
    __shared__ float Bs[16][128];

    const int tid = threadIdx.x;
    const int tx = tid & 15, ty = tid >> 4;
    const int m0 = blockIdx.y * 128;
    const int n0 = blockIdx.x * 128;

    float acc[8][8];
    #pragma unroll
    for (int i = 0; i < 8; i++)
        #pragma unroll
        for (int j = 0; j < 8; j++) acc[i][j] = 0.f;

    const int ra = tid >> 2, ca = (tid & 3) * 4;       // A loader
    const int rb = tid >> 5, cb = (tid & 31) * 4;      // B loader

    for (int k0 = 0; k0 < K; k0 += 16) {
        float4 a0 = *(const float4*)&A[(size_t)(m0 + ra) * K + k0 + ca];
        float4 a1 = *(const float4*)&A[(size_t)(m0 + ra + 64) * K + k0 + ca];
        As[ca + 0][ra] = a0.x; As[ca + 1][ra] = a0.y;
        As[ca + 2][ra] = a0.z; As[ca + 3][ra] = a0.w;
        As[ca + 0][ra + 64] = a1.x; As[ca + 1][ra + 64] = a1.y;
        As[ca + 2][ra + 64] = a1.z; As[ca + 3][ra + 64] = a1.w;
        *(float4*)&Bs[rb][cb]     = *(const float4*)&B[(size_t)(k0 + rb) * N + n0 + cb];
        *(float4*)&Bs[rb + 8][cb] = *(const float4*)&B[(size_t)(k0 + rb + 8) * N + n0 + cb];
        __syncthreads();

        #pragma unroll
        for (int k = 0; k < 16; k++) {
            float a[8], b[8];
            *(float4*)(a)     = *(const float4*)&As[k][ty * 8];
            *(float4*)(a + 4) = *(const float4*)&As[k][ty * 8 + 4];
            *(float4*)(b)     = *(const float4*)&Bs[k][tx * 8];
            *(float4*)(b + 4) = *(const float4*)&Bs[k][tx * 8 + 4];
            #pragma unroll
            for (int i = 0; i < 8; i++)
                #pragma unroll
                for (int j = 0; j < 8; j++)
                    acc[i][j] = fmaf(a[i], b[j], acc[i][j]);
        }
        __syncthreads();
    }

    if (EPI == 0) {
        const float* __restrict__ bias = g_b + (size_t)s * D;
        #pragma unroll
        for (int i = 0; i < 8; i++) {
            int m = m0 + ty * 8 + i;
            #pragma unroll
            for (int j = 0; j < 8; j += 4) {
                int n = n0 + tx * 8 + j;
                float4 v;
                v.x = acc[i][j + 0] + bias[n + 0];
                v.y = acc[i][j + 1] + bias[n + 1];
                v.z = acc[i][j + 2] + bias[n + 2];
                v.w = acc[i][j + 3] + bias[n + 3];
                *(float4*)&C[(size_t)m * N + n] = v;
            }
        }
    } else {
        #pragma unroll
        for (int i = 0; i < 8; i++) {
            int m = m0 + ty * 8 + i;
            float q2 = g_sqq[(size_t)s * NQ + m];
            #pragma unroll
            for (int j = 0; j < 8; j += 4) {
                int n = n0 + tx * 8 + j;
                float4 v;
                v.x = sqrtf(fmaxf(q2 + g_sqp[n + 0] - 2.f * acc[i][j + 0], 1e-12f));
                v.y = sqrtf(fmaxf(q2 + g_sqp[n + 1] - 2.f * acc[i][j + 1], 1e-12f));
                v.z = sqrtf(fmaxf(q2 + g_sqp[n + 2] - 2.f * acc[i][j + 2], 1e-12f));
                v.w = sqrtf(fmaxf(q2 + g_sqp[n + 3] - 2.f * acc[i][j + 3], 1e-12f));
                *(float4*)&C[(size_t)m * N + n] = v;
            }
        }
    }
}

// ------------------------------ reduction -----------------------------------
__global__ void reduce_kernel(float* __restrict__ out) {
    size_t i = (size_t)blockIdx.x * blockDim.x + threadIdx.x;   // over NQ*NP
    float v[S];
    float sum = 0.f;
    #pragma unroll
    for (int s = 0; s < S; s++) {
        v[s] = g_dists[(size_t)s * NQ * NP + i];
        sum += v[s];
    }
    float mean = sum * (1.0f / S);
    float m2 = 0.f;
    #pragma unroll
    for (int s = 0; s < S; s++) {
        float d = v[s] - mean;
        m2 = fmaf(d, d, m2);
    }
    out[i] = mean;
    out[(size_t)NQ * NP + i] = sqrtf(m2 * (1.0f / (S - 1)));
}

// ------------------------------ launcher ------------------------------------
extern "C" void kernel_launch(void* const* d_in, const int* in_sizes, int n_in,
                              void* d_out, int out_size) {
    const float* X    = (const float*)d_in[0];   // query_features [4096,512]
    const float* P    = (const float*)d_in[1];   // prototypes     [1024,512]
    const float* wmu  = (const float*)d_in[2];   // [512,512]
    const float* wrho = (const float*)d_in[3];   // [512,512]
    const float* bmu  = (const float*)d_in[4];   // [512]
    const float* brho = (const float*)d_in[5];   // [512]
    float* out = (float*)d_out;

    // jax.random.key(42) -> (0, 42); split -> kw, kb
    const unsigned key0 = 0u, key1 = 42u;
    unsigned kw0, kw1, kb0, kb1;
#if JAX_PARTITIONABLE
    { unsigned x0 = 0u, x1 = 0u; tf2x32(key0, key1, x0, x1); kw0 = x0; kw1 = x1; }
    { unsigned x0 = 0u, x1 = 1u; tf2x32(key0, key1, x0, x1); kb0 = x0; kb1 = x1; }
#else
    { unsigned a0 = 0u, a1 = 2u; tf2x32(key0, key1, a0, a1);
      unsigned b0 = 1u, b1 = 3u; tf2x32(key0, key1, b0, b1);
      kw0 = a0; kw1 = b0; kb0 = a1; kb1 = b1; }
#endif

    gen_w_kernel<<<(S * D * D) / 256, 256>>>(wmu, wrho, kw0, kw1);
    gen_b_kernel<<<(S * D) / 256, 256>>>(bmu, brho, kb0, kb1);
    prep_pt_kernel<<<(D * NP) / 256, 256>>>(P);
    sqp_kernel<<<NP / 8, 256>>>(P);

    gemm128<0><<<dim3(D / 128, NQ / 128, S), 256>>>(X);
    sqq_kernel<<<(S * NQ) / 8, 256>>>();
    gemm128<1><<<dim3(NP / 128, NQ / 128, S), 256>>>(X);

    reduce_kernel<<<(NQ * NP) / 256, 256>>>(out);
}